// round 10
// baseline (speedup 1.0000x reference)
#include <cuda_runtime.h>
#include <math.h>

#define BATCH 8
#define CIN   64
#define COUT  128
#define EDIM  128
#define HIN   192
#define WIN   384
#define OH    96
#define OW    192
#define TOPK  32
#define OUT6_SIZE (BATCH*COUT*OH*OW)
#define P2H 98
#define P2W 204

typedef unsigned long long u64;

__device__ float d_out2p[BATCH*TOPK*P2H*P2W];
__device__ int   d_idx1[BATCH*TOPK];
__device__ float d_gv1 [BATCH*TOPK];
__device__ int   d_idx2[BATCH*TOPK];
__device__ float d_gv2 [BATCH*TOPK];
__device__ int   d_slot2[BATCH*COUT];

__device__ __forceinline__ float leaky(float v) { return v >= 0.f ? v : 0.2f * v; }
__device__ __forceinline__ u64 pk2(float lo, float hi) {
    u64 r; asm("mov.b64 %0, {%1, %2};" : "=l"(r) : "f"(lo), "f"(hi)); return r;
}
__device__ __forceinline__ void upk2(u64 v, float& lo, float& hi) {
    asm("mov.b64 {%0, %1}, %2;" : "=f"(lo), "=f"(hi) : "l"(v));
}
__device__ __forceinline__ void fma2(u64& d, u64 a, u64 b) {
    asm("fma.rn.f32x2 %0, %1, %2, %0;" : "+l"(d) : "l"(a), "l"(b));
}
__device__ __forceinline__ unsigned smem_u32(const void* p) {
    return (unsigned)__cvta_generic_to_shared(p);
}
__device__ __forceinline__ void cp4(unsigned dst, const void* src, int sz) {
    asm volatile("cp.async.ca.shared.global [%0], [%1], 4, %2;" :: "r"(dst), "l"(src), "r"(sz));
}
__device__ __forceinline__ void cp16(unsigned dst, const void* src) {
    asm volatile("cp.async.ca.shared.global [%0], [%1], 16;" :: "r"(dst), "l"(src));
}
__device__ __forceinline__ void cp16s(unsigned dst, const void* src, int sz) {
    asm volatile("cp.async.ca.shared.global [%0], [%1], 16, %2;" :: "r"(dst), "l"(src), "r"(sz));
}
#define CP_COMMIT() asm volatile("cp.async.commit_group;")
#define CP_WAIT1()  asm volatile("cp.async.wait_group 1;")
#define CP_WAIT0()  asm volatile("cp.async.wait_group 0;")

// ============================================================================
// Gate (unchanged)
// ============================================================================
__global__ void gate_kernel(const float* __restrict__ emb,
                            const float* __restrict__ g1w, const float* __restrict__ g1b,
                            const float* __restrict__ g2w, const float* __restrict__ g2b,
                            float* __restrict__ out) {
    const int b    = blockIdx.x;
    const int gate = blockIdx.y;
    const int c    = threadIdx.x;
    const float* gw = (gate == 0) ? g1w : g2w;
    const float* gb = (gate == 0) ? g1b : g2b;

    __shared__ float s_emb[EDIM];
    __shared__ float s_log[COUT];
    __shared__ float s_exp[COUT];

    s_emb[c] = emb[b * EDIM + c];
    __syncthreads();

    float l = gb[c];
    #pragma unroll 8
    for (int e = 0; e < EDIM; e++) l += s_emb[e] * gw[e * COUT + c];
    s_log[c] = l;
    __syncthreads();

    int rank = 0;
    float m = -1e30f;
    for (int j = 0; j < COUT; j++) {
        float lj = s_log[j];
        if (lj > l || (lj == l && j < c)) rank++;
        if (lj > m) m = lj;
    }
    bool sel = (rank < TOPK);
    float ev = sel ? expf(l - m) : 0.0f;
    s_exp[c] = ev;
    __syncthreads();

    float s = 0.f;
    for (int j = 0; j < COUT; j++) s += s_exp[j];
    float gv = ev / s;

    out[OUT6_SIZE + gate * (BATCH * COUT) + b * COUT + c] = gv;

    if (gate == 0) {
        if (sel) { d_idx1[b * TOPK + rank] = c; d_gv1[b * TOPK + rank] = gv; }
    } else {
        d_slot2[b * COUT + c] = sel ? rank : -1;
        if (sel) { d_idx2[b * TOPK + rank] = c; d_gv2[b * TOPK + rank] = gv; }
    }
}

// ============================================================================
// FUSED conv1 + ds. grid (360, BATCH), block 256.
//   bx < 72 : conv1 3x3 s2 p1 -> d_out2p (R8 path, tile=bx)
//   bx >= 72: ds 1x1 s2 + BN (lean, 16 co per block, raw ident for gate2 chans)
// Co-resident blocks overlap conv1's FMA streams with ds's DRAM traffic.
// ============================================================================
#define C1_XSTR 68
__global__ void __launch_bounds__(256, 3) c1ds_kernel(const float* __restrict__ x,
                                                      const float* __restrict__ w1,
                                                      const float* __restrict__ dsw,
                                                      const float* __restrict__ gamma,
                                                      const float* __restrict__ beta,
                                                      float* __restrict__ out) {
    __shared__ int   s_idx[TOPK];
    __shared__ float s_gv[TOPK];
    __shared__ __align__(16) float s_w[2][4 * TOPK * 24];   // 24.6 KB
    __shared__ __align__(16) float s_x[2][17 * C1_XSTR];    // 9.2 KB
    __shared__ __align__(16) float ds_w[CIN][32];           // 8 KB
    __shared__ float ds_scale[16];
    __shared__ float ds_beta[16];
    __shared__ int   ds_slot[16];

    const int b   = blockIdx.y;
    const int tid = threadIdx.x;

    if (blockIdx.x >= 72) {
        // ---------------- ds path ----------------
        const int q    = blockIdx.x - 72;          // 0..287
        const int tile = q % 36, cgy = q / 36;     // 36 tiles of 8x64 px, 8 co-groups
        const int h0 = (tile / 3) * 8, w0 = (tile % 3) * 64;
        const int py = tid >> 5, px = tid & 31;
        const int h = h0 + py, w = w0 + 2 * px;

        for (int i = tid; i < CIN * 16; i += 256) {
            int ci = i >> 4, co = i & 15;
            float wv = dsw[(cgy * 16 + co) * CIN + ci];
            ds_w[ci][2 * co] = wv; ds_w[ci][2 * co + 1] = wv;
        }
        if (tid < 16) {
            int c = cgy * 16 + tid;
            ds_scale[tid] = gamma[c] * rsqrtf(1.0f + 1e-5f);
            ds_beta[tid]  = beta[c];
            ds_slot[tid]  = d_slot2[b * COUT + c];
        }
        __syncthreads();

        u64 acc[16];
        #pragma unroll
        for (int i = 0; i < 16; i++) acc[i] = 0ull;

        const float* xb = x + ((size_t)b * CIN * HIN + 2 * h) * WIN + 2 * w;
        #pragma unroll 8
        for (int ci = 0; ci < CIN; ci++) {
            float4 xv = *(const float4*)(xb + (size_t)ci * HIN * WIN);
            u64 xp = pk2(xv.x, xv.z);
            const u64* wr = (const u64*)&ds_w[ci][0];
            #pragma unroll
            for (int co = 0; co < 16; co += 2) {
                ulonglong2 qv = *(const ulonglong2*)(wr + co);
                fma2(acc[co],     xp, qv.x);
                fma2(acc[co + 1], xp, qv.y);
            }
        }

        #pragma unroll
        for (int co = 0; co < 16; co++) {
            int c = cgy * 16 + co;
            float v0, v1; upk2(acc[co], v0, v1);
            float sc = ds_scale[co], be = ds_beta[co];
            v0 = v0 * sc + be; v1 = v1 * sc + be;
            float2 o;
            if (ds_slot[co] < 0) { o.x = leaky(v0); o.y = leaky(v1); }
            else                 { o.x = v0;        o.y = v1; }   // raw; conv2 finishes it
            *(float2*)&out[((size_t)(b * COUT + c) * OH + h) * OW + w] = o;
        }
        return;
    }

    // ---------------- conv1 path (R8, tile=bx) ----------------
    const int tile = blockIdx.x;
    const int h0 = (tile / 6) * 8, w0 = (tile % 6) * 32;
    const int cog = tid >> 6;
    const int t   = tid & 63;
    const int row = t >> 3;
    const int c4  = t & 7;

    if (tid < TOPK) { s_idx[tid] = d_idx1[b * TOPK + tid]; s_gv[tid] = d_gv1[b * TOPK + tid]; }
    __syncthreads();

    u64 acc[8][2];
    #pragma unroll
    for (int i = 0; i < 8; i++) { acc[i][0] = 0ull; acc[i][1] = 0ull; }

    {
        for (int i = tid; i < 4 * TOPK * 9; i += 256) {
            int ci_l = i / (TOPK * 9);
            int r = i - ci_l * (TOPK * 9);
            int co = r / 9, k = r - co * 9;
            const float* src = w1 + (s_idx[co] * CIN + ci_l) * 9 + k;
            unsigned dst = smem_u32(&s_w[0][(ci_l * TOPK + co) * 24 + (k / 3) * 8 + (k % 3) * 2]);
            cp4(dst, src, 4); cp4(dst + 4, src, 4);
        }
        const float* sp = x + (size_t)(b * CIN + 0) * HIN * WIN;
        for (int i = tid; i < 289; i += 256) {
            int r = i / 17, u = i - r * 17;
            int gr = 2 * h0 - 1 + r, gc = 2 * w0 - 4 + 4 * u;
            int ok = (gr >= 0 && gc >= 0) ? 16 : 0;
            cp16s(smem_u32(&s_x[0][r * C1_XSTR + 4 * u]), sp + (size_t)gr * WIN + gc, ok);
        }
        CP_COMMIT();
    }

    for (int s = 0; s < CIN; s++) {
        if (s + 1 < CIN) {
            const int sn = s + 1;
            if ((sn & 3) == 0) {
                const int chunk = sn >> 2, wb = chunk & 1;
                for (int i = tid; i < 4 * TOPK * 9; i += 256) {
                    int ci_l = i / (TOPK * 9);
                    int r = i - ci_l * (TOPK * 9);
                    int co = r / 9, k = r - co * 9;
                    const float* src = w1 + (s_idx[co] * CIN + chunk * 4 + ci_l) * 9 + k;
                    unsigned dst = smem_u32(&s_w[wb][(ci_l * TOPK + co) * 24 + (k / 3) * 8 + (k % 3) * 2]);
                    cp4(dst, src, 4); cp4(dst + 4, src, 4);
                }
            }
            const float* sp = x + (size_t)(b * CIN + sn) * HIN * WIN;
            const int xb2 = sn & 1;
            for (int i = tid; i < 289; i += 256) {
                int r = i / 17, u = i - r * 17;
                int gr = 2 * h0 - 1 + r, gc = 2 * w0 - 4 + 4 * u;
                int ok = (gr >= 0 && gc >= 0) ? 16 : 0;
                cp16s(smem_u32(&s_x[xb2][r * C1_XSTR + 4 * u]), sp + (size_t)gr * WIN + gc, ok);
            }
            CP_COMMIT();
            CP_WAIT1();
        } else {
            CP_WAIT0();
        }
        __syncthreads();

        {
            const float* xp = &s_x[s & 1][(2 * row) * C1_XSTR + 8 * c4];
            const float* wcb = &s_w[(s >> 2) & 1][((s & 3) * TOPK + cog * 8) * 24];
            #pragma unroll
            for (int r = 0; r < 3; r++) {
                const float* rp = xp + r * C1_XSTR;
                float  p0 = rp[3];
                float4 A0 = *(const float4*)(rp + 4);
                float4 A1 = *(const float4*)(rp + 8);
                u64 S00 = pk2(p0,   A0.y);
                u64 S01 = pk2(A0.x, A0.z);
                u64 S02 = pk2(A0.y, A0.w);
                u64 S10 = pk2(A0.w, A1.y);
                u64 S11 = pk2(A1.x, A1.z);
                u64 S12 = pk2(A1.y, A1.w);
                #pragma unroll
                for (int j = 0; j < 8; j++) {
                    const u64* wp = (const u64*)(wcb + j * 24 + r * 8);
                    ulonglong2 qq = *(const ulonglong2*)wp;
                    u64 q2 = wp[2];
                    fma2(acc[j][0], S00, qq.x);
                    fma2(acc[j][0], S01, qq.y);
                    fma2(acc[j][0], S02, q2);
                    fma2(acc[j][1], S10, qq.x);
                    fma2(acc[j][1], S11, qq.y);
                    fma2(acc[j][1], S12, q2);
                }
            }
        }
        __syncthreads();
    }

    const int h = h0 + row, w = w0 + 4 * c4;
    #pragma unroll
    for (int j = 0; j < 8; j++) {
        int co = cog * 8 + j;
        float g = s_gv[co];
        float v0, v1, v2, v3;
        upk2(acc[j][0], v0, v1);
        upk2(acc[j][1], v2, v3);
        float4 o;
        o.x = leaky(v0 * g); o.y = leaky(v1 * g);
        o.z = leaky(v2 * g); o.w = leaky(v3 * g);
        *(float4*)&d_out2p[((size_t)(b * TOPK + co) * P2H + h + 1) * P2W + (w + 4)] = o;
    }
}

// ============================================================================
// conv2 (unchanged R8): fused leaky(leaky(conv*g2)+ident). grid (72, BATCH).
// ============================================================================
#define C2_XSTR 40
__global__ void __launch_bounds__(256, 3) conv2_kernel(const float* __restrict__ w2,
                                                       float* __restrict__ out) {
    const int b = blockIdx.y, tile = blockIdx.x;
    const int h0 = (tile / 6) * 8, w0 = (tile % 6) * 32;
    const int tid = threadIdx.x;
    const int cog = tid >> 6;
    const int t   = tid & 63;
    const int row = t >> 3;
    const int c4  = t & 7;

    __shared__ int   s_idx1[TOPK];
    __shared__ int   s_idx2[TOPK];
    __shared__ float s_gv[TOPK];
    __shared__ __align__(16) float s_w[2][4 * TOPK * 24];
    __shared__ __align__(16) float s_x[2][10 * C2_XSTR];

    if (tid < TOPK) {
        s_idx1[tid] = d_idx1[b * TOPK + tid];
        s_idx2[tid] = d_idx2[b * TOPK + tid];
        s_gv[tid]   = d_gv2[b * TOPK + tid];
    }
    __syncthreads();

    u64 acc[8][2];
    #pragma unroll
    for (int i = 0; i < 8; i++) { acc[i][0] = 0ull; acc[i][1] = 0ull; }

    {
        for (int i = tid; i < 4 * TOPK * 9; i += 256) {
            int ci_l = i / (TOPK * 9);
            int r = i - ci_l * (TOPK * 9);
            int co = r / 9, k = r - co * 9;
            const float* src = w2 + (s_idx2[co] * COUT + s_idx1[ci_l]) * 9 + k;
            unsigned dst = smem_u32(&s_w[0][(ci_l * TOPK + co) * 24 + (k / 3) * 8 + (k % 3) * 2]);
            cp4(dst, src, 4); cp4(dst + 4, src, 4);
        }
        const float* sp = d_out2p + (size_t)(b * TOPK + 0) * P2H * P2W;
        for (int i = tid; i < 100; i += 256) {
            int r = i / 10, u = i - r * 10;
            cp16(smem_u32(&s_x[0][r * C2_XSTR + 4 * u]), sp + (size_t)(h0 + r) * P2W + w0 + 4 * u);
        }
        CP_COMMIT();
    }

    for (int s = 0; s < TOPK; s++) {
        if (s + 1 < TOPK) {
            const int sn = s + 1;
            if ((sn & 3) == 0) {
                const int chunk = sn >> 2, wb = chunk & 1;
                for (int i = tid; i < 4 * TOPK * 9; i += 256) {
                    int ci_l = i / (TOPK * 9);
                    int r = i - ci_l * (TOPK * 9);
                    int co = r / 9, k = r - co * 9;
                    const float* src = w2 + (s_idx2[co] * COUT + s_idx1[chunk * 4 + ci_l]) * 9 + k;
                    unsigned dst = smem_u32(&s_w[wb][(ci_l * TOPK + co) * 24 + (k / 3) * 8 + (k % 3) * 2]);
                    cp4(dst, src, 4); cp4(dst + 4, src, 4);
                }
            }
            const float* sp = d_out2p + (size_t)(b * TOPK + sn) * P2H * P2W;
            const int xb2 = sn & 1;
            for (int i = tid; i < 100; i += 256) {
                int r = i / 10, u = i - r * 10;
                cp16(smem_u32(&s_x[xb2][r * C2_XSTR + 4 * u]), sp + (size_t)(h0 + r) * P2W + w0 + 4 * u);
            }
            CP_COMMIT();
            CP_WAIT1();
        } else {
            CP_WAIT0();
        }
        __syncthreads();

        {
            const float* xp = &s_x[s & 1][row * C2_XSTR + 4 * c4];
            const float* wcb = &s_w[(s >> 2) & 1][((s & 3) * TOPK + cog * 8) * 24];
            #pragma unroll
            for (int r = 0; r < 3; r++) {
                const float* rp = xp + r * C2_XSTR;
                float  d0 = rp[3];
                float4 A  = *(const float4*)(rp + 4);
                float  d5 = rp[8];
                u64 Q0 = pk2(d0,  A.x);
                u64 Q1 = pk2(A.x, A.y);
                u64 Q2 = pk2(A.y, A.z);
                u64 Q3 = pk2(A.z, A.w);
                u64 Q4 = pk2(A.w, d5);
                #pragma unroll
                for (int j = 0; j < 8; j++) {
                    const u64* wp = (const u64*)(wcb + j * 24 + r * 8);
                    ulonglong2 qq = *(const ulonglong2*)wp;
                    u64 q2 = wp[2];
                    fma2(acc[j][0], Q0, qq.x);
                    fma2(acc[j][0], Q1, qq.y);
                    fma2(acc[j][0], Q2, q2);
                    fma2(acc[j][1], Q2, qq.x);
                    fma2(acc[j][1], Q3, qq.y);
                    fma2(acc[j][1], Q4, q2);
                }
            }
        }
        __syncthreads();
    }

    const int h = h0 + row, w = w0 + 4 * c4;
    #pragma unroll
    for (int j = 0; j < 8; j++) {
        int co = cog * 8 + j;
        float g = s_gv[co];
        int c = s_idx2[co];
        float* base = &out[((size_t)(b * COUT + c) * OH + h) * OW + w];
        float4 id = *(const float4*)base;
        float v0, v1, v2, v3;
        upk2(acc[j][0], v0, v1);
        upk2(acc[j][1], v2, v3);
        float4 o;
        o.x = leaky(leaky(v0 * g) + id.x);
        o.y = leaky(leaky(v1 * g) + id.y);
        o.z = leaky(leaky(v2 * g) + id.z);
        o.w = leaky(leaky(v3 * g) + id.w);
        *(float4*)base = o;
    }
}

// ============================================================================
extern "C" void kernel_launch(void* const* d_in, const int* in_sizes, int n_in,
                              void* d_out, int out_size) {
    const float* x     = (const float*)d_in[0];
    const float* emb   = (const float*)d_in[1];
    const float* w1    = (const float*)d_in[2];
    const float* w2    = (const float*)d_in[3];
    const float* dsw   = (const float*)d_in[4];
    const float* gam   = (const float*)d_in[5];
    const float* bet   = (const float*)d_in[6];
    const float* g1w   = (const float*)d_in[7];
    const float* g1b   = (const float*)d_in[8];
    const float* g2w   = (const float*)d_in[9];
    const float* g2b   = (const float*)d_in[10];
    float* out = (float*)d_out;

    gate_kernel<<<dim3(BATCH, 2), 128>>>(emb, g1w, g1b, g2w, g2b, out);
    c1ds_kernel<<<dim3(360, BATCH), 256>>>(x, w1, dsw, gam, bet, out);
    conv2_kernel<<<dim3(72, BATCH), 256>>>(w2, out);
}

// round 11
// speedup vs baseline: 1.3405x; 1.3405x over previous
#include <cuda_runtime.h>
#include <cuda_bf16.h>
#include <math.h>
#include <stdint.h>

#define BATCH 8
#define CIN   64
#define COUT  128
#define EDIM  128
#define HIN   192
#define WIN   384
#define OH    96
#define OW    192
#define TOPK  32
#define OUT6_SIZE (BATCH*COUT*OH*OW)

typedef unsigned long long u64;
typedef unsigned int u32;

// x NHWC bf16, zero halos: row = input row + 1 (193), px = input col + 1 (385), 64 ci
#define XTROWS 193
#define XTPX   385
// conv1 out NHWC bf16: pr = h+1 (98), pc = w+1 (194), 32 ci
#define O2R 98
#define O2PX 194

__device__ __nv_bfloat16 d_xt[(size_t)BATCH*XTROWS*XTPX*64];
__device__ __nv_bfloat16 d_o2[(size_t)BATCH*O2R*O2PX*32];
__device__ __nv_bfloat16 d_w1p[BATCH*576*32];
__device__ __nv_bfloat16 d_w2p[BATCH*288*32];
__device__ int   d_idx1[BATCH*TOPK];
__device__ float d_gv1 [BATCH*TOPK];
__device__ int   d_idx2[BATCH*TOPK];
__device__ float d_gv2 [BATCH*TOPK];
__device__ int   d_slot2[BATCH*COUT];

__device__ __forceinline__ float leaky(float v) { return v >= 0.f ? v : 0.2f * v; }
__device__ __forceinline__ u64 pk2(float lo, float hi) {
    u64 r; asm("mov.b64 %0, {%1, %2};" : "=l"(r) : "f"(lo), "f"(hi)); return r;
}
__device__ __forceinline__ void upk2(u64 v, float& lo, float& hi) {
    asm("mov.b64 {%0, %1}, %2;" : "=f"(lo), "=f"(hi) : "l"(v));
}
__device__ __forceinline__ void fma2(u64& d, u64 a, u64 b) {
    asm("fma.rn.f32x2 %0, %1, %2, %0;" : "+l"(d) : "l"(a), "l"(b));
}
__device__ __forceinline__ unsigned smem_u32(const void* p) {
    return (unsigned)__cvta_generic_to_shared(p);
}
__device__ __forceinline__ void cp4(unsigned dst, const void* src, int sz) {
    asm volatile("cp.async.ca.shared.global [%0], [%1], 4, %2;" :: "r"(dst), "l"(src), "r"(sz));
}
__device__ __forceinline__ void cp16(unsigned dst, const void* src) {
    asm volatile("cp.async.ca.shared.global [%0], [%1], 16;" :: "r"(dst), "l"(src));
}
#define CP_COMMIT() asm volatile("cp.async.commit_group;")
#define CP_WAIT0()  asm volatile("cp.async.wait_group 0;")

__device__ __forceinline__ void ldsm_x4(u32* r, unsigned a) {
    asm volatile("ldmatrix.sync.aligned.m8n8.x4.shared.b16 {%0,%1,%2,%3}, [%4];"
        : "=r"(r[0]), "=r"(r[1]), "=r"(r[2]), "=r"(r[3]) : "r"(a));
}
__device__ __forceinline__ void ldsm_x2t(u32* r, unsigned a) {
    asm volatile("ldmatrix.sync.aligned.m8n8.x2.trans.shared.b16 {%0,%1}, [%2];"
        : "=r"(r[0]), "=r"(r[1]) : "r"(a));
}
__device__ __forceinline__ void mma_bf16(float* d, const u32* a, const u32* b) {
    asm volatile("mma.sync.aligned.m16n8k16.row.col.f32.bf16.bf16.f32 "
        "{%0,%1,%2,%3}, {%4,%5,%6,%7}, {%8,%9}, {%0,%1,%2,%3};"
        : "+f"(d[0]), "+f"(d[1]), "+f"(d[2]), "+f"(d[3])
        : "r"(a[0]), "r"(a[1]), "r"(a[2]), "r"(a[3]), "r"(b[0]), "r"(b[1]));
}

// ============================================================================
// xt: x NCHW f32 -> d_xt NHWC bf16 (zero halos untouched). grid (6,192,8), 256.
// ============================================================================
__global__ void __launch_bounds__(256) xt_kernel(const float* __restrict__ x) {
    const int wc = blockIdx.x, r = blockIdx.y, b = blockIdx.z;
    const int w0 = wc * 64;
    const int tid = threadIdx.x;
    __shared__ float s[64][65];
    #pragma unroll 4
    for (int i = tid; i < 4096; i += 256) {
        int ci = i >> 6, w = i & 63;
        s[ci][w] = x[((size_t)(b * 64 + ci) * HIN + r) * WIN + w0 + w];
    }
    __syncthreads();
    const int px = tid >> 2, q = tid & 3;
    u32 pk[8];
    #pragma unroll
    for (int j = 0; j < 8; j++) {
        __nv_bfloat162 t = __floats2bfloat162_rn(s[q * 16 + 2 * j][px], s[q * 16 + 2 * j + 1][px]);
        pk[j] = *(u32*)&t;
    }
    uint4* dst = (uint4*)(d_xt + (((size_t)(b * XTROWS + r + 1) * XTPX + w0 + px + 1) * 64 + q * 16));
    dst[0] = make_uint4(pk[0], pk[1], pk[2], pk[3]);
    dst[1] = make_uint4(pk[4], pk[5], pk[6], pk[7]);
}

// ============================================================================
// Gate (unchanged)
// ============================================================================
__global__ void gate_kernel(const float* __restrict__ emb,
                            const float* __restrict__ g1w, const float* __restrict__ g1b,
                            const float* __restrict__ g2w, const float* __restrict__ g2b,
                            float* __restrict__ out) {
    const int b = blockIdx.x, gate = blockIdx.y, c = threadIdx.x;
    const float* gw = (gate == 0) ? g1w : g2w;
    const float* gb = (gate == 0) ? g1b : g2b;
    __shared__ float s_emb[EDIM];
    __shared__ float s_log[COUT];
    __shared__ float s_exp[COUT];
    s_emb[c] = emb[b * EDIM + c];
    __syncthreads();
    float l = gb[c];
    #pragma unroll 8
    for (int e = 0; e < EDIM; e++) l += s_emb[e] * gw[e * COUT + c];
    s_log[c] = l;
    __syncthreads();
    int rank = 0; float m = -1e30f;
    for (int j = 0; j < COUT; j++) {
        float lj = s_log[j];
        if (lj > l || (lj == l && j < c)) rank++;
        if (lj > m) m = lj;
    }
    bool sel = (rank < TOPK);
    float ev = sel ? expf(l - m) : 0.0f;
    s_exp[c] = ev;
    __syncthreads();
    float s = 0.f;
    for (int j = 0; j < COUT; j++) s += s_exp[j];
    float gv = ev / s;
    out[OUT6_SIZE + gate * (BATCH * COUT) + b * COUT + c] = gv;
    if (gate == 0) {
        if (sel) { d_idx1[b * TOPK + rank] = c; d_gv1[b * TOPK + rank] = gv; }
    } else {
        d_slot2[b * COUT + c] = sel ? rank : -1;
        if (sel) { d_idx2[b * TOPK + rank] = c; d_gv2[b * TOPK + rank] = gv; }
    }
}

// ============================================================================
// wpack: gather + gate-scale weights into [k][co] bf16, per batch. grid 8, 256.
// w1p: k = tap*64+ci (K=576). w2p: k = tap*32+ci_l (K=288). Gate folded in.
// ============================================================================
__global__ void __launch_bounds__(256) wpack_kernel(const float* __restrict__ w1,
                                                    const float* __restrict__ w2) {
    const int b = blockIdx.x, tid = threadIdx.x;
    for (int i = tid; i < 32 * 576; i += 256) {
        int co = i / 576, kk = i - co * 576;
        int ci = kk / 9, tap = kk - ci * 9;
        float v = w1[((size_t)d_idx1[b * 32 + co] * 64 + ci) * 9 + tap] * d_gv1[b * 32 + co];
        d_w1p[(size_t)b * 18432 + (tap * 64 + ci) * 32 + co] = __float2bfloat16(v);
    }
    for (int i = tid; i < 32 * 288; i += 256) {
        int co = i / 288, kk = i - co * 288;
        int ci = kk / 9, tap = kk - ci * 9;
        float v = w2[((size_t)d_idx2[b * 32 + co] * 128 + d_idx1[b * 32 + ci]) * 9 + tap] * d_gv2[b * 32 + co];
        d_w2p[(size_t)b * 9216 + (tap * 32 + ci) * 32 + co] = __float2bfloat16(v);
    }
}

// ============================================================================
// ds (unchanged R8): fp32, all 128 co/block; raw ident for gate2 channels.
// ============================================================================
#define DS_SMEM ((8192 + 8192 + 384) * 4)
__global__ void __launch_bounds__(256, 2) ds_kernel(const float* __restrict__ x,
                                                    const float* __restrict__ dsw,
                                                    const float* __restrict__ gamma,
                                                    const float* __restrict__ beta,
                                                    float* __restrict__ out) {
    extern __shared__ __align__(16) float dsm[];
    float* s_xc    = dsm;
    float* s_wt    = dsm + 8192;
    float* s_scale = dsm + 16384;
    float* s_betav = s_scale + 128;
    int*   s_slot  = (int*)(s_betav + 128);

    const int b  = blockIdx.y;
    const int h0 = (blockIdx.x / 12) * 8;
    const int w0 = (blockIdx.x % 12) * 16;
    const int tid = threadIdx.x;
    const int po  = tid >> 4;
    const int cg  = tid & 15;

    const float* xb = x + (size_t)b * CIN * HIN * WIN;
    #pragma unroll 8
    for (int k = 0; k < 32; k++) {
        int i = tid + k * 256;
        int ci = i >> 7, p = i & 127, r = (p >> 4), j = p & 15;
        cp4(smem_u32(&s_xc[i]), xb + (size_t)ci * HIN * WIN + (2 * (h0 + r)) * WIN + 2 * (w0 + j), 4);
    }
    #pragma unroll 8
    for (int k = 0; k < 32; k++) {
        int i = tid + k * 256;
        int co = i >> 6, ci = i & 63;
        cp4(smem_u32(&s_wt[ci * 128 + co]), dsw + i, 4);
    }
    if (tid < 128) {
        s_scale[tid] = gamma[tid] * rsqrtf(1.0f + 1e-5f);
        s_betav[tid] = beta[tid];
        s_slot[tid]  = d_slot2[b * COUT + tid];
    }
    CP_COMMIT(); CP_WAIT0();
    __syncthreads();

    u64 acc[8][4];
    #pragma unroll
    for (int c = 0; c < 8; c++)
        #pragma unroll
        for (int m = 0; m < 4; m++) acc[c][m] = 0ull;

    #pragma unroll 4
    for (int ci = 0; ci < 64; ci++) {
        const ulonglong2* xq = (const ulonglong2*)&s_xc[ci * 128 + 8 * po];
        ulonglong2 X0 = xq[0], X1 = xq[1];
        const float4* wq = (const float4*)&s_wt[ci * 128 + 8 * cg];
        float4 wa = wq[0], wb2 = wq[1];
        u64 W[8];
        W[0] = pk2(wa.x, wa.x);   W[1] = pk2(wa.y, wa.y);
        W[2] = pk2(wa.z, wa.z);   W[3] = pk2(wa.w, wa.w);
        W[4] = pk2(wb2.x, wb2.x); W[5] = pk2(wb2.y, wb2.y);
        W[6] = pk2(wb2.z, wb2.z); W[7] = pk2(wb2.w, wb2.w);
        #pragma unroll
        for (int c = 0; c < 8; c++) {
            fma2(acc[c][0], X0.x, W[c]);
            fma2(acc[c][1], X0.y, W[c]);
            fma2(acc[c][2], X1.x, W[c]);
            fma2(acc[c][3], X1.y, W[c]);
        }
    }

    const int hr  = h0 + (po >> 1);
    const int wc0 = w0 + (po & 1) * 8;
    #pragma unroll
    for (int c = 0; c < 8; c++) {
        int co = 8 * cg + c;
        float v[8];
        #pragma unroll
        for (int m = 0; m < 4; m++) upk2(acc[c][m], v[2 * m], v[2 * m + 1]);
        float sc = s_scale[co], be = s_betav[co];
        #pragma unroll
        for (int k = 0; k < 8; k++) v[k] = v[k] * sc + be;
        if (s_slot[co] < 0) {
            #pragma unroll
            for (int k = 0; k < 8; k++) v[k] = leaky(v[k]);
        }
        float* base = &out[((size_t)(b * COUT + co) * OH + hr) * OW + wc0];
        *(float4*)base       = make_float4(v[0], v[1], v[2], v[3]);
        *(float4*)(base + 4) = make_float4(v[4], v[5], v[6], v[7]);
    }
}

// ============================================================================
// conv1_tc: 3x3 s2 p1 via mma.sync bf16. Block = 96 out px of one row.
// grid (2, 96, BATCH), 192 thr (6 warps x 1 m16-tile x 4 n8). K = 576.
// ============================================================================
#define C1_ROWB (XTPX * 128)                      // 49280 B per staged row
#define C1_SMEM (3 * 193 * 128 + 18432 * 2)      // 74112 + 36864 = 110976
__global__ void __launch_bounds__(192, 2) conv1_tc() {
    extern __shared__ __align__(16) char sm1[];
    char* sx = sm1;                                // 3 rows x 193 px x 128B
    char* sw = sm1 + 3 * 193 * 128;                // [576][32] bf16
    float* sep = (float*)sm1;                      // epilogue reuse [96][33]

    const int half = blockIdx.x, h = blockIdx.y, b = blockIdx.z;
    const int w0 = half * 96;
    const int tid = threadIdx.x, wid = tid >> 5, lane = tid & 31;

    // stage 3 xt rows (rows 2h..2h+2, px 2w0..2w0+192) + weights
    {
        const char* xb = (const char*)(d_xt + (((size_t)(b * XTROWS + 2 * h) * XTPX + 2 * w0) * 64));
        for (int i = tid; i < 3 * 1544; i += 192) {
            int r = i / 1544, off = (i - r * 1544) * 16;
            cp16(smem_u32(sx + r * (193 * 128) + off), xb + (size_t)r * C1_ROWB + off);
        }
        const char* wb = (const char*)(d_w1p + (size_t)b * 18432);
        for (int i = tid; i < 2304; i += 192)
            cp16(smem_u32(sw + i * 16), wb + i * 16);
        CP_COMMIT(); CP_WAIT0();
    }
    __syncthreads();

    float acc[4][4];
    #pragma unroll
    for (int n = 0; n < 4; n++)
        #pragma unroll
        for (int k = 0; k < 4; k++) acc[n][k] = 0.f;

    const int moff = lane & 15;
    const int kbyte = (lane < 16) ? 0 : 16;
    const int mpx = wid * 16 + moff;               // local out-w index 0..95
    const unsigned sxb = smem_u32(sx);
    const unsigned swb = smem_u32(sw);
    const int brow0 = (lane & 15) * 64;

    #pragma unroll 4
    for (int kc = 0; kc < 36; kc++) {
        const int tap = kc >> 2, cc = kc & 3;
        const int dh = tap / 3, dw = tap - 3 * dh;
        u32 a[4];
        ldsm_x4(a, sxb + dh * (193 * 128) + (2 * mpx + dw) * 128 + cc * 32 + kbyte);
        const unsigned bbase = swb + kc * 16 * 64 + brow0;
        #pragma unroll
        for (int n = 0; n < 4; n++) {
            u32 bb[2];
            ldsm_x2t(bb, bbase + n * 16);
            mma_bf16(acc[n], a, bb);
        }
    }
    __syncthreads();

    // acc -> sep[px][33] (gate already folded into weights)
    const int gid = lane >> 2, tig = lane & 3;
    #pragma unroll
    for (int n = 0; n < 4; n++) {
        int co = n * 8 + 2 * tig;
        int p0 = wid * 16 + gid;
        sep[p0 * 33 + co]           = acc[n][0];
        sep[p0 * 33 + co + 1]       = acc[n][1];
        sep[(p0 + 8) * 33 + co]     = acc[n][2];
        sep[(p0 + 8) * 33 + co + 1] = acc[n][3];
    }
    __syncthreads();

    // write d_o2 NHWC bf16, coalesced 32B per thread
    const int px = tid >> 1, hc = tid & 1;
    u32 pk[8];
    #pragma unroll
    for (int j = 0; j < 8; j++) {
        float v0 = leaky(sep[px * 33 + hc * 16 + 2 * j]);
        float v1 = leaky(sep[px * 33 + hc * 16 + 2 * j + 1]);
        __nv_bfloat162 t = __floats2bfloat162_rn(v0, v1);
        pk[j] = *(u32*)&t;
    }
    uint4* dst = (uint4*)(d_o2 + (((size_t)(b * O2R + h + 1) * O2PX + 1 + w0 + px) * 32 + hc * 16));
    dst[0] = make_uint4(pk[0], pk[1], pk[2], pk[3]);
    dst[1] = make_uint4(pk[4], pk[5], pk[6], pk[7]);
}

// ============================================================================
// conv2_tc: 3x3 s1 p1 via mma.sync bf16; epilogue leaky(leaky(v)+ident) fused.
// Block = 192 out px of one row. grid (96, BATCH), 192 thr (6 warps x 2 m16 x 4 n8).
// ============================================================================
#define C2_ROWB (O2PX * 64)                        // 12416 B per staged row
#define C2_SMEM (3 * C2_ROWB + 9216 * 2)           // 37248 + 18432 = 55680
__global__ void __launch_bounds__(192, 3) conv2_tc(float* __restrict__ out) {
    extern __shared__ __align__(16) char sm2[];
    char* sx = sm2;                                // 3 rows x 194 px x 64B
    char* sw = sm2 + 3 * C2_ROWB;                  // [288][32] bf16
    float* sep = (float*)sm2;                      // epilogue reuse [192][33]
    __shared__ int s_idx2s[32];

    const int h = blockIdx.x, b = blockIdx.y;
    const int tid = threadIdx.x, wid = tid >> 5, lane = tid & 31;

    {
        const char* xb = (const char*)(d_o2 + ((size_t)(b * O2R + h) * O2PX) * 32);
        for (int i = tid; i < 3 * 776; i += 192) {
            int r = i / 776, off = (i - r * 776) * 16;
            cp16(smem_u32(sx + r * C2_ROWB + off), xb + (size_t)r * C2_ROWB + off);
        }
        const char* wb = (const char*)(d_w2p + (size_t)b * 9216);
        for (int i = tid; i < 1152; i += 192)
            cp16(smem_u32(sw + i * 16), wb + i * 16);
        if (tid < 32) s_idx2s[tid] = d_idx2[b * 32 + tid];
        CP_COMMIT(); CP_WAIT0();
    }
    __syncthreads();

    float acc[2][4][4];
    #pragma unroll
    for (int mi = 0; mi < 2; mi++)
        #pragma unroll
        for (int n = 0; n < 4; n++)
            #pragma unroll
            for (int k = 0; k < 4; k++) acc[mi][n][k] = 0.f;

    const int moff = lane & 15;
    const int kbyte = (lane < 16) ? 0 : 16;
    const unsigned sxb = smem_u32(sx);
    const unsigned swb = smem_u32(sw);
    const int brow0 = (lane & 15) * 64;

    #pragma unroll 3
    for (int kc = 0; kc < 18; kc++) {
        const int tap = kc >> 1, cc = kc & 1;
        const int dh = tap / 3, dw = tap - 3 * dh;
        u32 bb[4][2];
        const unsigned bbase = swb + kc * 16 * 64 + brow0;
        #pragma unroll
        for (int n = 0; n < 4; n++) ldsm_x2t(bb[n], bbase + n * 16);
        #pragma unroll
        for (int mi = 0; mi < 2; mi++) {
            u32 a[4];
            const int p = (2 * wid + mi) * 16 + moff + dw;   // staged px index
            ldsm_x4(a, sxb + dh * C2_ROWB + p * 64 + cc * 32 + kbyte);
            #pragma unroll
            for (int n = 0; n < 4; n++) mma_bf16(acc[mi][n], a, bb[n]);
        }
    }
    __syncthreads();

    const int gid = lane >> 2, tig = lane & 3;
    #pragma unroll
    for (int mi = 0; mi < 2; mi++) {
        int p0 = (2 * wid + mi) * 16 + gid;
        #pragma unroll
        for (int n = 0; n < 4; n++) {
            int co = n * 8 + 2 * tig;
            sep[p0 * 33 + co]           = acc[mi][n][0];
            sep[p0 * 33 + co + 1]       = acc[mi][n][1];
            sep[(p0 + 8) * 33 + co]     = acc[mi][n][2];
            sep[(p0 + 8) * 33 + co + 1] = acc[mi][n][3];
        }
    }
    __syncthreads();

    // fused epilogue: out = leaky(leaky(conv*g2) + ident_raw), coalesced per co
    for (int co = 0; co < 32; co++) {
        float v = sep[tid * 33 + co];
        float* op = &out[((size_t)(b * COUT + s_idx2s[co]) * OH + h) * OW + tid];
        *op = leaky(leaky(v) + *op);
    }
}

// ============================================================================
extern "C" void kernel_launch(void* const* d_in, const int* in_sizes, int n_in,
                              void* d_out, int out_size) {
    const float* x     = (const float*)d_in[0];
    const float* emb   = (const float*)d_in[1];
    const float* w1    = (const float*)d_in[2];
    const float* w2    = (const float*)d_in[3];
    const float* dsw   = (const float*)d_in[4];
    const float* gam   = (const float*)d_in[5];
    const float* bet   = (const float*)d_in[6];
    const float* g1w   = (const float*)d_in[7];
    const float* g1b   = (const float*)d_in[8];
    const float* g2w   = (const float*)d_in[9];
    const float* g2b   = (const float*)d_in[10];
    float* out = (float*)d_out;

    cudaFuncSetAttribute(ds_kernel,  cudaFuncAttributeMaxDynamicSharedMemorySize, DS_SMEM);
    cudaFuncSetAttribute(conv1_tc,   cudaFuncAttributeMaxDynamicSharedMemorySize, C1_SMEM);
    cudaFuncSetAttribute(conv2_tc,   cudaFuncAttributeMaxDynamicSharedMemorySize, C2_SMEM);

    xt_kernel<<<dim3(6, 192, BATCH), 256>>>(x);
    gate_kernel<<<dim3(BATCH, 2), 128>>>(emb, g1w, g1b, g2w, g2b, out);
    wpack_kernel<<<BATCH, 256>>>(w1, w2);
    ds_kernel<<<dim3(144, BATCH), 256, DS_SMEM>>>(x, dsw, gam, bet, out);
    conv1_tc<<<dim3(2, OH, BATCH), 192, C1_SMEM>>>();
    conv2_tc<<<dim3(OH, BATCH), 192, C2_SMEM>>>(out);
}